// round 13
// baseline (speedup 1.0000x reference)
#include <cuda_runtime.h>
#include <cuda_bf16.h>
#include <cuda_fp16.h>
#include <cstdint>

#define Bv 4
#define Sv 1024
#define Hv 2048
#define Nv 16
#define Dv 128
#define NCOL 2304          // 18 * 128 fused output columns (16 Q heads, K, V)

// ---------------- device scratch (static: allocation-free) ------------------
__device__ __align__(16) unsigned short g_Ahi[(size_t)Bv * Sv * Hv];
__device__ __align__(16) unsigned short g_Alo[(size_t)Bv * Sv * Hv];
__device__ __align__(16) unsigned short g_Bhi[(size_t)NCOL * Hv];
__device__ __align__(16) unsigned short g_Blo[(size_t)NCOL * Hv];
__device__ __align__(16) unsigned short g_Qh[(size_t)Bv * Nv * Sv * Dv];
__device__ __align__(16) unsigned short g_Ql[(size_t)Bv * Nv * Sv * Dv];
__device__ __align__(16) unsigned short g_Kh[(size_t)Bv * Sv * Dv];
__device__ __align__(16) unsigned short g_Kl[(size_t)Bv * Sv * Dv];
__device__ __align__(16) __half         g_Vf[(size_t)Bv * Sv * Dv];

// ---------------- helpers ----------------------------------------------------
__device__ __forceinline__ uint32_t smem_u32(const void* p) {
    uint32_t a;
    asm("{ .reg .u64 t; cvta.to.shared.u64 t, %1; cvt.u32.u64 %0, t; }"
        : "=r"(a) : "l"(p));
    return a;
}
__device__ __forceinline__ uint32_t sw128(uint32_t b) {
    return b ^ ((b >> 3) & 0x70);
}
__device__ __forceinline__ uint32_t sw64(uint32_t b) {
    return b ^ (((b >> 7) & 3u) << 4);
}
#define CP16(dst, src) asm volatile( \
    "cp.async.cg.shared.global [%0], [%1], 16;" :: "r"(dst), "l"(src))
#define CP_COMMIT() asm volatile("cp.async.commit_group;" ::: "memory")
#define CP_WAIT0() asm volatile("cp.async.wait_group 0;" ::: "memory")
#define CP_WAIT1() asm volatile("cp.async.wait_group 1;" ::: "memory")

__device__ __forceinline__ void ldsm4(uint32_t addr, uint32_t* r) {
    asm volatile("ldmatrix.sync.aligned.m8n8.x4.shared.b16 {%0,%1,%2,%3}, [%4];"
                 : "=r"(r[0]), "=r"(r[1]), "=r"(r[2]), "=r"(r[3]) : "r"(addr));
}
__device__ __forceinline__ void ldsm4t(uint32_t addr, uint32_t* r) {
    asm volatile("ldmatrix.sync.aligned.m8n8.x4.trans.shared.b16 {%0,%1,%2,%3}, [%4];"
                 : "=r"(r[0]), "=r"(r[1]), "=r"(r[2]), "=r"(r[3]) : "r"(addr));
}
__device__ __forceinline__ void mma16816(float* d, const uint32_t* a,
                                         const uint32_t* b) {
    asm volatile(
        "mma.sync.aligned.m16n8k16.row.col.f32.bf16.bf16.f32 "
        "{%0,%1,%2,%3}, {%4,%5,%6,%7}, {%8,%9}, {%0,%1,%2,%3};"
        : "+f"(d[0]), "+f"(d[1]), "+f"(d[2]), "+f"(d[3])
        : "r"(a[0]), "r"(a[1]), "r"(a[2]), "r"(a[3]), "r"(b[0]), "r"(b[1]));
}
__device__ __forceinline__ void mma16816h(float* d, const uint32_t* a,
                                          const uint32_t* b) {
    asm volatile(
        "mma.sync.aligned.m16n8k16.row.col.f32.f16.f16.f32 "
        "{%0,%1,%2,%3}, {%4,%5,%6,%7}, {%8,%9}, {%0,%1,%2,%3};"
        : "+f"(d[0]), "+f"(d[1]), "+f"(d[2]), "+f"(d[3])
        : "r"(a[0]), "r"(a[1]), "r"(a[2]), "r"(a[3]), "r"(b[0]), "r"(b[1]));
}

__device__ __forceinline__ void split_bf16(float x, unsigned short& h,
                                           unsigned short& l) {
    __nv_bfloat16 hb = __float2bfloat16_rn(x);
    __nv_bfloat16 lb = __float2bfloat16_rn(x - __bfloat162float(hb));
    h = *(unsigned short*)&hb;
    l = *(unsigned short*)&lb;
}
__device__ __forceinline__ uint32_t pack_h2(float a, float b) {
    __half2 h = __floats2half2_rn(a, b);
    return *(uint32_t*)&h;
}

// ---------------------------------------------------------------------------
// Convert 1: hidden_states -> hi/lo bf16 (row-major [4096, 2048])
// ---------------------------------------------------------------------------
__global__ void conv_a_kernel(const float* __restrict__ hs) {
    size_t i4 = (size_t)blockIdx.x * blockDim.x + threadIdx.x;
    float4 x = *(const float4*)&hs[i4 * 4];
    unsigned short h[4], l[4];
    split_bf16(x.x, h[0], l[0]);
    split_bf16(x.y, h[1], l[1]);
    split_bf16(x.z, h[2], l[2]);
    split_bf16(x.w, h[3], l[3]);
    *(uint2*)&g_Ahi[i4 * 4] = *(uint2*)h;
    *(uint2*)&g_Alo[i4 * 4] = *(uint2*)l;
}

// ---------------------------------------------------------------------------
// Convert 2: W -> K-major Bt [2304, 2048]: Bt[u*128+d][k] = W_u[k][d]
// ---------------------------------------------------------------------------
__global__ void conv_b_kernel(const float* __restrict__ Wq,
                              const float* __restrict__ Wk,
                              const float* __restrict__ Wv) {
    __shared__ float t[32][33];
    int n0 = blockIdx.x * 32;
    int k0 = blockIdx.y * 32;
    int u = n0 >> 7;
    int d0 = n0 & 127;
    const float* W = (u < Nv) ? (Wq + (size_t)u * Hv * Dv)
                              : ((u == Nv) ? Wk : Wv);
#pragma unroll
    for (int i = 0; i < 4; i++) {
        int k = k0 + threadIdx.y + i * 8;
        t[threadIdx.y + i * 8][threadIdx.x] = W[(size_t)k * Dv + d0 + threadIdx.x];
    }
    __syncthreads();
#pragma unroll
    for (int i = 0; i < 4; i++) {
        int r = threadIdx.y + i * 8;
        float v = t[threadIdx.x][r];
        unsigned short h, l;
        split_bf16(v, h, l);
        size_t o = (size_t)(n0 + r) * Hv + k0 + threadIdx.x;
        g_Bhi[o] = h;
        g_Blo[o] = l;
    }
}

// ---------------------------------------------------------------------------
// bf16x3 projection GEMM (HMMA), v4: 2 CTAs/SM + 3-stage pipeline.
// CTA tile 128x128 (grid 32 x 18), 128 threads, 4 warps = 2(M) x 2(N),
// warp tile 64x64, k32 chunks (SW64). 3 stages x 32KB = 96KB/CTA.
// Loop: wait_group<=1 (chunk c done, c+1 may be in flight) -> sync ->
// issue load c+2 -> compute c.  Load latency fully hidden behind compute.
// ---------------------------------------------------------------------------
#define PSTAGE 32768
#define NCHUNK 64

__global__ __launch_bounds__(128, 2) void proj_mma_kernel(
    const float* __restrict__ bq, const float* __restrict__ bk,
    const float* __restrict__ bv)
{
    extern __shared__ __align__(1024) char smem[];
    const int tid = threadIdx.x;
    const int lane = tid & 31;
    const int w = tid >> 5;
    const int wm = w & 1;
    const int wn = w >> 1;
    const int m0 = blockIdx.x * 128;
    const int by = blockIdx.y;
    const int n0 = by * 128;
    const uint32_t sbase = smem_u32(smem);

    float acc[4][8][4];
#pragma unroll
    for (int mt = 0; mt < 4; mt++)
#pragma unroll
        for (int nt = 0; nt < 8; nt++)
#pragma unroll
            for (int i = 0; i < 4; i++) acc[mt][nt][i] = 0.f;

    auto stage_of = [&](int c) -> uint32_t {
        int s = c % 3;
        return sbase + (uint32_t)s * PSTAGE;
    };

    auto load_chunk = [&](int c) {
        const uint32_t sb = stage_of(c);
        const int k0 = c * 32;
#pragma unroll
        for (int i = 0; i < 4; i++) {
            int idx = tid + 128 * i;
            int r = idx >> 2, col = idx & 3;
            uint32_t off = sw64(r * 64 + col * 16);
            CP16(sb + off,         &g_Ahi[(size_t)(m0 + r) * Hv + k0 + col * 8]);
            CP16(sb + 8192 + off,  &g_Alo[(size_t)(m0 + r) * Hv + k0 + col * 8]);
            CP16(sb + 16384 + off, &g_Bhi[(size_t)(n0 + r) * Hv + k0 + col * 8]);
            CP16(sb + 24576 + off, &g_Blo[(size_t)(n0 + r) * Hv + k0 + col * 8]);
        }
    };

    const int a_row = wm * 64 + (lane & 15);
    const int a_k16 = lane >> 4;
    const int b_row0 = wn * 64 + (lane & 7) + ((lane >> 4) << 3);
    const int b_k16 = (lane >> 3) & 1;

    load_chunk(0);
    CP_COMMIT();
    load_chunk(1);
    CP_COMMIT();

    for (int c = 0; c < NCHUNK; c++) {
        const uint32_t sb = stage_of(c);
        CP_WAIT1();                 // chunk c landed (c+1 may be in flight)
        __syncthreads();            // all warps done with stage (c) % 3 reuse
        if (c + 2 < NCHUNK) {
            load_chunk(c + 2);      // stage (c+2)%3: last computed at c-1
            CP_COMMIT();
        }

#pragma unroll
        for (int ks = 0; ks < 2; ks++) {
            uint32_t ah[4][4], al[4][4], bh[4][4], bl[4][4];
#pragma unroll
            for (int mt = 0; mt < 4; mt++) {
                uint32_t off = sw64((a_row + mt * 16) * 64 +
                                    (ks * 2 + a_k16) * 16);
                ldsm4(sb + off, ah[mt]);
                ldsm4(sb + 8192 + off, al[mt]);
            }
#pragma unroll
            for (int p = 0; p < 4; p++) {
                uint32_t off = sw64((b_row0 + p * 16) * 64 +
                                    (ks * 2 + b_k16) * 16);
                ldsm4(sb + 16384 + off, bh[p]);
                ldsm4(sb + 24576 + off, bl[p]);
            }
#pragma unroll
            for (int mt = 0; mt < 4; mt++)
#pragma unroll
                for (int nt = 0; nt < 8; nt++) {
                    const uint32_t* bhp = &bh[nt >> 1][(nt & 1) * 2];
                    const uint32_t* blp = &bl[nt >> 1][(nt & 1) * 2];
                    mma16816(acc[mt][nt], ah[mt], bhp);
                    mma16816(acc[mt][nt], al[mt], bhp);
                    mma16816(acc[mt][nt], ah[mt], blp);
                }
        }
    }

    const int u = by;
    const float* bias = (u < Nv) ? (bq + u * Dv) : ((u == Nv) ? bk : bv);
    const int qrow = lane >> 2;
    const int qcol = (lane & 3) * 2;

#pragma unroll
    for (int mt = 0; mt < 4; mt++) {
#pragma unroll
        for (int half = 0; half < 2; half++) {
            int mrow = m0 + wm * 64 + mt * 16 + qrow + half * 8;
            size_t base;
            if (u < Nv) {
                int b = mrow >> 10, s = mrow & 1023;
                base = ((size_t)(b * Nv + u) * Sv + s) * Dv;
            } else {
                base = (size_t)mrow * Dv;
            }
#pragma unroll
            for (int nt = 0; nt < 8; nt++) {
                int d = wn * 64 + nt * 8 + qcol;
                float x = acc[mt][nt][half * 2 + 0] + bias[d];
                float y = acc[mt][nt][half * 2 + 1] + bias[d + 1];
                if (u < Nv) {
                    unsigned short hx, lx, hy, ly;
                    split_bf16(x, hx, lx);
                    split_bf16(y, hy, ly);
                    *(ushort2*)&g_Qh[base + d] = make_ushort2(hx, hy);
                    *(ushort2*)&g_Ql[base + d] = make_ushort2(lx, ly);
                } else if (u == Nv) {
                    unsigned short hx, lx, hy, ly;
                    split_bf16(x, hx, lx);
                    split_bf16(y, hy, ly);
                    *(ushort2*)&g_Kh[base + d] = make_ushort2(hx, hy);
                    *(ushort2*)&g_Kl[base + d] = make_ushort2(lx, ly);
                } else {
                    __half2 v2 = __floats2half2_rn(x, y);
                    *(__half2*)&g_Vf[base + d] = v2;
                }
            }
        }
    }
}

// ---------------------------------------------------------------------------
// Tensor-core flash attention (R12 form — best measured: 181.9us, 3 CTAs/SM).
// 128 threads (4 warps x 16 q-rows), 32-key KV tiles, 64KB smem/CTA.
// ---------------------------------------------------------------------------
#define KV_TILE 24576
#define NKV (Sv / 32)

__global__ __launch_bounds__(128, 3) void attn_mma_kernel(float* __restrict__ out)
{
    extern __shared__ __align__(1024) char smem[];
    const int tid = threadIdx.x;
    const int lane = tid & 31;
    const int w = tid >> 5;
    const int qt = blockIdx.x;
    const int n = blockIdx.y;
    const int b = blockIdx.z;

    const uint32_t sQl = smem_u32(smem);
    const uint32_t sKV = sQl + 16384;

    const size_t qoff = ((size_t)(b * Nv + n) * Sv + qt * 64) * Dv;
    const unsigned short* Qhp = g_Qh + qoff;
    const unsigned short* Qlp = g_Ql + qoff;
#pragma unroll
    for (int i = 0; i < 8; i++) {
        int idx = tid + 128 * i;
        int r = idx >> 4, c16 = idx & 15;
        uint32_t off = (uint32_t)(c16 >> 3) * 8192 +
                       sw128(r * 128 + (c16 & 7) * 16);
        CP16(sKV + off, Qhp + (size_t)r * Dv + c16 * 8);
        CP16(sQl + off, Qlp + (size_t)r * Dv + c16 * 8);
    }
    CP_COMMIT();
    CP_WAIT0();
    __syncthreads();

    uint32_t ah[8][4];
#pragma unroll
    for (int kk = 0; kk < 8; kk++) {
        uint32_t qo = (uint32_t)(kk >> 2) * 8192 +
            sw128((w * 16 + (lane & 15)) * 128 +
                  ((kk & 3) * 2 + (lane >> 4)) * 16);
        ldsm4(sKV + qo, ah[kk]);
    }
    __syncthreads();

    const unsigned short* Kh = g_Kh + (size_t)b * Sv * Dv;
    const unsigned short* Kl = g_Kl + (size_t)b * Sv * Dv;
    const __half* Vf = g_Vf + (size_t)b * Sv * Dv;

    auto load_kv = [&](int t) {
        uint32_t dst = sKV + (uint32_t)(t & 1) * KV_TILE;
        int r0 = t * 32;
#pragma unroll
        for (int i = 0; i < 4; i++) {
            int idx = tid + 128 * i;
            int r = idx >> 4, c16 = idx & 15;
            uint32_t off = (uint32_t)(c16 >> 3) * 4096 +
                           sw128(r * 128 + (c16 & 7) * 16);
            CP16(dst + off,         Kh + (size_t)(r0 + r) * Dv + c16 * 8);
            CP16(dst + 8192 + off,  Kl + (size_t)(r0 + r) * Dv + c16 * 8);
            CP16(dst + 16384 + off, Vf + (size_t)(r0 + r) * Dv + c16 * 8);
        }
    };

    load_kv(0);
    CP_COMMIT();

    float o[16][4];
#pragma unroll
    for (int nt = 0; nt < 16; nt++)
#pragma unroll
        for (int i = 0; i < 4; i++) o[nt][i] = 0.f;
    float mrun[2] = {-3.0e38f, -3.0e38f};
    float lrun[2] = {0.f, 0.f};

    for (int t = 0; t < NKV; t++) {
        CP_WAIT0();
        __syncthreads();
        if (t + 1 < NKV) {
            load_kv(t + 1);
            CP_COMMIT();
        }
        const uint32_t kb = sKV + (uint32_t)(t & 1) * KV_TILE;

        float s[4][4];
#pragma unroll
        for (int nt = 0; nt < 4; nt++)
#pragma unroll
            for (int i = 0; i < 4; i++) s[nt][i] = 0.f;

#pragma unroll
        for (int kk = 0; kk < 8; kk++) {
            uint32_t qo = (uint32_t)(kk >> 2) * 8192 +
                sw128((w * 16 + (lane & 15)) * 128 +
                      ((kk & 3) * 2 + (lane >> 4)) * 16);
            uint32_t alf[4];
            ldsm4(sQl + qo, alf);
            uint32_t kcol = ((kk & 3) * 2 + ((lane >> 3) & 1)) * 16;
#pragma unroll
            for (int p = 0; p < 2; p++) {
                uint32_t ko = (uint32_t)(kk >> 2) * 4096 +
                    sw128((p * 16 + (lane & 7) + ((lane >> 4) << 3)) * 128 + kcol);
                uint32_t bh[4], bl[4];
                ldsm4(kb + ko, bh);
                ldsm4(kb + 8192 + ko, bl);
#pragma unroll
                for (int q = 0; q < 2; q++) {
                    int nt = p * 2 + q;
                    mma16816(s[nt], ah[kk], &bh[q * 2]);
                    mma16816(s[nt], alf,    &bh[q * 2]);
                    mma16816(s[nt], ah[kk], &bl[q * 2]);
                }
            }
        }

        float tmax[2] = {-3.0e38f, -3.0e38f};
#pragma unroll
        for (int nt = 0; nt < 4; nt++) {
            tmax[0] = fmaxf(tmax[0], fmaxf(s[nt][0], s[nt][1]));
            tmax[1] = fmaxf(tmax[1], fmaxf(s[nt][2], s[nt][3]));
        }
#pragma unroll
        for (int off = 1; off <= 2; off <<= 1) {
            tmax[0] = fmaxf(tmax[0], __shfl_xor_sync(0xffffffffu, tmax[0], off));
            tmax[1] = fmaxf(tmax[1], __shfl_xor_sync(0xffffffffu, tmax[1], off));
        }
        float mnew[2], ci[2];
#pragma unroll
        for (int h = 0; h < 2; h++) {
            mnew[h] = fmaxf(mrun[h], tmax[h]);
            ci[h] = __expf(mrun[h] - mnew[h]);
            mrun[h] = mnew[h];
        }
        uint32_t plo[4], phi[4];
        float rs0 = 0.f, rs1 = 0.f;
#pragma unroll
        for (int nt = 0; nt < 4; nt++) {
            float p0 = __expf(s[nt][0] - mnew[0]);
            float p1 = __expf(s[nt][1] - mnew[0]);
            float p2 = __expf(s[nt][2] - mnew[1]);
            float p3 = __expf(s[nt][3] - mnew[1]);
            rs0 += p0 + p1;
            rs1 += p2 + p3;
            plo[nt] = pack_h2(p0, p1);
            phi[nt] = pack_h2(p2, p3);
        }
        lrun[0] = lrun[0] * ci[0] + rs0;
        lrun[1] = lrun[1] * ci[1] + rs1;
#pragma unroll
        for (int nt = 0; nt < 16; nt++) {
            o[nt][0] *= ci[0];
            o[nt][1] *= ci[0];
            o[nt][2] *= ci[1];
            o[nt][3] *= ci[1];
        }

#pragma unroll
        for (int kk2 = 0; kk2 < 2; kk2++) {
            uint32_t a[4] = {plo[2 * kk2], phi[2 * kk2],
                             plo[2 * kk2 + 1], phi[2 * kk2 + 1]};
            uint32_t kvr = kk2 * 16 + (lane & 7) + (((lane >> 3) & 1) << 3);
#pragma unroll
            for (int dt = 0; dt < 8; dt++) {
                uint32_t dcol = dt * 16 + ((lane >> 4) << 3);
                uint32_t off = (uint32_t)(dcol >> 6) * 4096 +
                               sw128(kvr * 128 + (dcol & 63) * 2);
                uint32_t bv4[4];
                ldsm4t(kb + 16384 + off, bv4);
                mma16816h(o[dt * 2],     a, &bv4[0]);
                mma16816h(o[dt * 2 + 1], a, &bv4[2]);
            }
        }
    }

#pragma unroll
    for (int off = 1; off <= 2; off <<= 1) {
        lrun[0] += __shfl_xor_sync(0xffffffffu, lrun[0], off);
        lrun[1] += __shfl_xor_sync(0xffffffffu, lrun[1], off);
    }
    const float inv0 = 1.0f / lrun[0];
    const float inv1 = 1.0f / lrun[1];
    const int row0 = qt * 64 + w * 16 + (lane >> 2);
    const size_t ob = ((size_t)(b * Nv + n) * Sv) * Dv;
#pragma unroll
    for (int nt = 0; nt < 16; nt++) {
        int d = nt * 8 + (lane & 3) * 2;
        *(float2*)&out[ob + (size_t)row0 * Dv + d] =
            make_float2(o[nt][0] * inv0, o[nt][1] * inv0);
        *(float2*)&out[ob + (size_t)(row0 + 8) * Dv + d] =
            make_float2(o[nt][2] * inv1, o[nt][3] * inv1);
    }
}

// ---------------------------------------------------------------------------
extern "C" void kernel_launch(void* const* d_in, const int* in_sizes, int n_in,
                              void* d_out, int out_size)
{
    const float* hs = (const float*)d_in[0];
    const float* Wq = (const float*)d_in[1];
    const float* bq = (const float*)d_in[2];
    const float* Wk = (const float*)d_in[3];
    const float* bk = (const float*)d_in[4];
    const float* Wv = (const float*)d_in[5];
    const float* bv = (const float*)d_in[6];
    float* out = (float*)d_out;

    conv_a_kernel<<<(Bv * Sv * Hv / 4) / 256, 256>>>(hs);
    conv_b_kernel<<<dim3(NCOL / 32, Hv / 32), dim3(32, 8)>>>(Wq, Wk, Wv);

    const int proj_smem = 3 * PSTAGE;   // 96 KB -> 2 CTAs/SM, 3-stage pipe
    cudaFuncSetAttribute(proj_mma_kernel,
                         cudaFuncAttributeMaxDynamicSharedMemorySize, proj_smem);
    proj_mma_kernel<<<dim3(32, 18), 128, proj_smem>>>(bq, bk, bv);

    const int attn_smem = 16384 + 2 * KV_TILE;   // 64 KB -> 3 CTAs/SM
    cudaFuncSetAttribute(attn_mma_kernel,
                         cudaFuncAttributeMaxDynamicSharedMemorySize, attn_smem);
    dim3 ga(Sv / 64, Nv, Bv);
    attn_mma_kernel<<<ga, 128, attn_smem>>>(out);
}

// round 14
// speedup vs baseline: 1.0423x; 1.0423x over previous
#include <cuda_runtime.h>
#include <cuda_bf16.h>
#include <cuda_fp16.h>
#include <cstdint>

#define Bv 4
#define Sv 1024
#define Hv 2048
#define Nv 16
#define Dv 128
#define NCOL 2304          // 18 * 128 fused output columns (16 Q heads, K, V)

// ---------------- device scratch (static: allocation-free) ------------------
__device__ __align__(16) unsigned short g_Ahi[(size_t)Bv * Sv * Hv];
__device__ __align__(16) unsigned short g_Alo[(size_t)Bv * Sv * Hv];
__device__ __align__(16) unsigned short g_Bhi[(size_t)NCOL * Hv];
__device__ __align__(16) unsigned short g_Blo[(size_t)NCOL * Hv];
__device__ __align__(16) unsigned short g_Qh[(size_t)Bv * Nv * Sv * Dv];
__device__ __align__(16) unsigned short g_Ql[(size_t)Bv * Nv * Sv * Dv];
__device__ __align__(16) unsigned short g_Kh[(size_t)Bv * Sv * Dv];
__device__ __align__(16) unsigned short g_Kl[(size_t)Bv * Sv * Dv];
__device__ __align__(16) __half         g_Vf[(size_t)Bv * Sv * Dv];

// ---------------- helpers ----------------------------------------------------
__device__ __forceinline__ uint32_t smem_u32(const void* p) {
    uint32_t a;
    asm("{ .reg .u64 t; cvta.to.shared.u64 t, %1; cvt.u32.u64 %0, t; }"
        : "=r"(a) : "l"(p));
    return a;
}
__device__ __forceinline__ uint32_t sw128(uint32_t b) {
    return b ^ ((b >> 3) & 0x70);
}
__device__ __forceinline__ uint32_t sw64(uint32_t b) {
    return b ^ (((b >> 7) & 3u) << 4);
}
#define CP16(dst, src) asm volatile( \
    "cp.async.cg.shared.global [%0], [%1], 16;" :: "r"(dst), "l"(src))
#define CP_COMMIT() asm volatile("cp.async.commit_group;" ::: "memory")
#define CP_WAIT0() asm volatile("cp.async.wait_group 0;" ::: "memory")

__device__ __forceinline__ void ldsm4(uint32_t addr, uint32_t* r) {
    asm volatile("ldmatrix.sync.aligned.m8n8.x4.shared.b16 {%0,%1,%2,%3}, [%4];"
                 : "=r"(r[0]), "=r"(r[1]), "=r"(r[2]), "=r"(r[3]) : "r"(addr));
}
__device__ __forceinline__ void ldsm4t(uint32_t addr, uint32_t* r) {
    asm volatile("ldmatrix.sync.aligned.m8n8.x4.trans.shared.b16 {%0,%1,%2,%3}, [%4];"
                 : "=r"(r[0]), "=r"(r[1]), "=r"(r[2]), "=r"(r[3]) : "r"(addr));
}
__device__ __forceinline__ void mma16816(float* d, const uint32_t* a,
                                         const uint32_t* b) {
    asm volatile(
        "mma.sync.aligned.m16n8k16.row.col.f32.bf16.bf16.f32 "
        "{%0,%1,%2,%3}, {%4,%5,%6,%7}, {%8,%9}, {%0,%1,%2,%3};"
        : "+f"(d[0]), "+f"(d[1]), "+f"(d[2]), "+f"(d[3])
        : "r"(a[0]), "r"(a[1]), "r"(a[2]), "r"(a[3]), "r"(b[0]), "r"(b[1]));
}
__device__ __forceinline__ void mma16816h(float* d, const uint32_t* a,
                                          const uint32_t* b) {
    asm volatile(
        "mma.sync.aligned.m16n8k16.row.col.f32.f16.f16.f32 "
        "{%0,%1,%2,%3}, {%4,%5,%6,%7}, {%8,%9}, {%0,%1,%2,%3};"
        : "+f"(d[0]), "+f"(d[1]), "+f"(d[2]), "+f"(d[3])
        : "r"(a[0]), "r"(a[1]), "r"(a[2]), "r"(a[3]), "r"(b[0]), "r"(b[1]));
}

__device__ __forceinline__ void split_bf16(float x, unsigned short& h,
                                           unsigned short& l) {
    __nv_bfloat16 hb = __float2bfloat16_rn(x);
    __nv_bfloat16 lb = __float2bfloat16_rn(x - __bfloat162float(hb));
    h = *(unsigned short*)&hb;
    l = *(unsigned short*)&lb;
}
__device__ __forceinline__ uint32_t pack_h2(float a, float b) {
    __half2 h = __floats2half2_rn(a, b);
    return *(uint32_t*)&h;
}

// ---------------------------------------------------------------------------
// Merged convert kernel: one launch covers both phases.
// Blocks [0, CONVA_BLOCKS): hidden_states -> Ahi/Alo (vectorized split).
// Blocks [CONVA_BLOCKS, ...): W transpose -> Bhi/Blo (32x32 smem tiles).
// ---------------------------------------------------------------------------
#define CONVA_BLOCKS ((Bv * Sv * Hv / 4) / 256)          // 8192
#define CONVB_BLOCKS ((NCOL / 32) * (Hv / 32))           // 72 * 64 = 4608

__global__ void conv_kernel(const float* __restrict__ hs,
                            const float* __restrict__ Wq,
                            const float* __restrict__ Wk,
                            const float* __restrict__ Wv) {
    __shared__ float t[32][33];
    const int bid = blockIdx.x;
    const int tid = threadIdx.x;

    if (bid < CONVA_BLOCKS) {
        size_t i4 = (size_t)bid * 256 + tid;
        float4 x = *(const float4*)&hs[i4 * 4];
        unsigned short h[4], l[4];
        split_bf16(x.x, h[0], l[0]);
        split_bf16(x.y, h[1], l[1]);
        split_bf16(x.z, h[2], l[2]);
        split_bf16(x.w, h[3], l[3]);
        *(uint2*)&g_Ahi[i4 * 4] = *(uint2*)h;
        *(uint2*)&g_Alo[i4 * 4] = *(uint2*)l;
        return;
    }

    const int bid2 = bid - CONVA_BLOCKS;
    const int n0 = (bid2 % (NCOL / 32)) * 32;
    const int k0 = (bid2 / (NCOL / 32)) * 32;
    const int tx = tid & 31;
    const int ty = tid >> 5;              // 0..7
    const int u = n0 >> 7;
    const int d0 = n0 & 127;
    const float* W = (u < Nv) ? (Wq + (size_t)u * Hv * Dv)
                              : ((u == Nv) ? Wk : Wv);
#pragma unroll
    for (int i = 0; i < 4; i++) {
        int k = k0 + ty + i * 8;
        t[ty + i * 8][tx] = W[(size_t)k * Dv + d0 + tx];
    }
    __syncthreads();
#pragma unroll
    for (int i = 0; i < 4; i++) {
        int r = ty + i * 8;
        float v = t[tx][r];
        unsigned short h, l;
        split_bf16(v, h, l);
        size_t o = (size_t)(n0 + r) * Hv + k0 + tx;
        g_Bhi[o] = h;
        g_Blo[o] = l;
    }
}

// ---------------------------------------------------------------------------
// bf16x3 projection GEMM (HMMA), 2 CTAs/SM, 2-stage pipeline (R11 form —
// best measured). CTA tile 128x128 (grid 32 x 18), 128 threads,
// 4 warps = 2(M) x 2(N), warp tile 64x64, k32 chunks (SW64).
// ---------------------------------------------------------------------------
#define PSTAGE 32768
#define NCHUNK 64

__global__ __launch_bounds__(128, 2) void proj_mma_kernel(
    const float* __restrict__ bq, const float* __restrict__ bk,
    const float* __restrict__ bv)
{
    extern __shared__ __align__(1024) char smem[];
    const int tid = threadIdx.x;
    const int lane = tid & 31;
    const int w = tid >> 5;
    const int wm = w & 1;
    const int wn = w >> 1;
    const int m0 = blockIdx.x * 128;
    const int by = blockIdx.y;
    const int n0 = by * 128;
    const uint32_t sbase = smem_u32(smem);

    float acc[4][8][4];
#pragma unroll
    for (int mt = 0; mt < 4; mt++)
#pragma unroll
        for (int nt = 0; nt < 8; nt++)
#pragma unroll
            for (int i = 0; i < 4; i++) acc[mt][nt][i] = 0.f;

    auto load_chunk = [&](uint32_t sb, int c) {
        const int k0 = c * 32;
#pragma unroll
        for (int i = 0; i < 4; i++) {
            int idx = tid + 128 * i;
            int r = idx >> 2, col = idx & 3;
            uint32_t off = sw64(r * 64 + col * 16);
            CP16(sb + off,         &g_Ahi[(size_t)(m0 + r) * Hv + k0 + col * 8]);
            CP16(sb + 8192 + off,  &g_Alo[(size_t)(m0 + r) * Hv + k0 + col * 8]);
            CP16(sb + 16384 + off, &g_Bhi[(size_t)(n0 + r) * Hv + k0 + col * 8]);
            CP16(sb + 24576 + off, &g_Blo[(size_t)(n0 + r) * Hv + k0 + col * 8]);
        }
    };

    const int a_row = wm * 64 + (lane & 15);
    const int a_k16 = lane >> 4;
    const int b_row0 = wn * 64 + (lane & 7) + ((lane >> 4) << 3);
    const int b_k16 = (lane >> 3) & 1;

    load_chunk(sbase, 0);
    CP_COMMIT();

    for (int c = 0; c < NCHUNK; c++) {
        const uint32_t sb = sbase + (uint32_t)(c & 1) * PSTAGE;
        CP_WAIT0();
        __syncthreads();
        if (c + 1 < NCHUNK) {
            load_chunk(sbase + (uint32_t)((c + 1) & 1) * PSTAGE, c + 1);
            CP_COMMIT();
        }

#pragma unroll
        for (int ks = 0; ks < 2; ks++) {
            uint32_t ah[4][4], al[4][4], bh[4][4], bl[4][4];
#pragma unroll
            for (int mt = 0; mt < 4; mt++) {
                uint32_t off = sw64((a_row + mt * 16) * 64 +
                                    (ks * 2 + a_k16) * 16);
                ldsm4(sb + off, ah[mt]);
                ldsm4(sb + 8192 + off, al[mt]);
            }
#pragma unroll
            for (int p = 0; p < 4; p++) {
                uint32_t off = sw64((b_row0 + p * 16) * 64 +
                                    (ks * 2 + b_k16) * 16);
                ldsm4(sb + 16384 + off, bh[p]);
                ldsm4(sb + 24576 + off, bl[p]);
            }
#pragma unroll
            for (int mt = 0; mt < 4; mt++)
#pragma unroll
                for (int nt = 0; nt < 8; nt++) {
                    const uint32_t* bhp = &bh[nt >> 1][(nt & 1) * 2];
                    const uint32_t* blp = &bl[nt >> 1][(nt & 1) * 2];
                    mma16816(acc[mt][nt], ah[mt], bhp);
                    mma16816(acc[mt][nt], al[mt], bhp);
                    mma16816(acc[mt][nt], ah[mt], blp);
                }
        }
    }

    const int u = by;
    const float* bias = (u < Nv) ? (bq + u * Dv) : ((u == Nv) ? bk : bv);
    const int qrow = lane >> 2;
    const int qcol = (lane & 3) * 2;

#pragma unroll
    for (int mt = 0; mt < 4; mt++) {
#pragma unroll
        for (int half = 0; half < 2; half++) {
            int mrow = m0 + wm * 64 + mt * 16 + qrow + half * 8;
            size_t base;
            if (u < Nv) {
                int b = mrow >> 10, s = mrow & 1023;
                base = ((size_t)(b * Nv + u) * Sv + s) * Dv;
            } else {
                base = (size_t)mrow * Dv;
            }
#pragma unroll
            for (int nt = 0; nt < 8; nt++) {
                int d = wn * 64 + nt * 8 + qcol;
                float x = acc[mt][nt][half * 2 + 0] + bias[d];
                float y = acc[mt][nt][half * 2 + 1] + bias[d + 1];
                if (u < Nv) {
                    unsigned short hx, lx, hy, ly;
                    split_bf16(x, hx, lx);
                    split_bf16(y, hy, ly);
                    *(ushort2*)&g_Qh[base + d] = make_ushort2(hx, hy);
                    *(ushort2*)&g_Ql[base + d] = make_ushort2(lx, ly);
                } else if (u == Nv) {
                    unsigned short hx, lx, hy, ly;
                    split_bf16(x, hx, lx);
                    split_bf16(y, hy, ly);
                    *(ushort2*)&g_Kh[base + d] = make_ushort2(hx, hy);
                    *(ushort2*)&g_Kl[base + d] = make_ushort2(lx, ly);
                } else {
                    __half2 v2 = __floats2half2_rn(x, y);
                    *(__half2*)&g_Vf[base + d] = v2;
                }
            }
        }
    }
}

// ---------------------------------------------------------------------------
// Tensor-core flash attention (R12 form — best kernel-level: 181.9us).
// 128 threads (4 warps x 16 q-rows), 32-key KV tiles, 64KB smem/CTA,
// 3 CTAs/SM (__launch_bounds__(128,3), 168 regs).
// ---------------------------------------------------------------------------
#define KV_TILE 24576
#define NKV (Sv / 32)

__global__ __launch_bounds__(128, 3) void attn_mma_kernel(float* __restrict__ out)
{
    extern __shared__ __align__(1024) char smem[];
    const int tid = threadIdx.x;
    const int lane = tid & 31;
    const int w = tid >> 5;
    const int qt = blockIdx.x;
    const int n = blockIdx.y;
    const int b = blockIdx.z;

    const uint32_t sQl = smem_u32(smem);
    const uint32_t sKV = sQl + 16384;

    const size_t qoff = ((size_t)(b * Nv + n) * Sv + qt * 64) * Dv;
    const unsigned short* Qhp = g_Qh + qoff;
    const unsigned short* Qlp = g_Ql + qoff;
#pragma unroll
    for (int i = 0; i < 8; i++) {
        int idx = tid + 128 * i;
        int r = idx >> 4, c16 = idx & 15;
        uint32_t off = (uint32_t)(c16 >> 3) * 8192 +
                       sw128(r * 128 + (c16 & 7) * 16);
        CP16(sKV + off, Qhp + (size_t)r * Dv + c16 * 8);
        CP16(sQl + off, Qlp + (size_t)r * Dv + c16 * 8);
    }
    CP_COMMIT();
    CP_WAIT0();
    __syncthreads();

    uint32_t ah[8][4];
#pragma unroll
    for (int kk = 0; kk < 8; kk++) {
        uint32_t qo = (uint32_t)(kk >> 2) * 8192 +
            sw128((w * 16 + (lane & 15)) * 128 +
                  ((kk & 3) * 2 + (lane >> 4)) * 16);
        ldsm4(sKV + qo, ah[kk]);
    }
    __syncthreads();

    const unsigned short* Kh = g_Kh + (size_t)b * Sv * Dv;
    const unsigned short* Kl = g_Kl + (size_t)b * Sv * Dv;
    const __half* Vf = g_Vf + (size_t)b * Sv * Dv;

    auto load_kv = [&](int t) {
        uint32_t dst = sKV + (uint32_t)(t & 1) * KV_TILE;
        int r0 = t * 32;
#pragma unroll
        for (int i = 0; i < 4; i++) {
            int idx = tid + 128 * i;
            int r = idx >> 4, c16 = idx & 15;
            uint32_t off = (uint32_t)(c16 >> 3) * 4096 +
                           sw128(r * 128 + (c16 & 7) * 16);
            CP16(dst + off,         Kh + (size_t)(r0 + r) * Dv + c16 * 8);
            CP16(dst + 8192 + off,  Kl + (size_t)(r0 + r) * Dv + c16 * 8);
            CP16(dst + 16384 + off, Vf + (size_t)(r0 + r) * Dv + c16 * 8);
        }
    };

    load_kv(0);
    CP_COMMIT();

    float o[16][4];
#pragma unroll
    for (int nt = 0; nt < 16; nt++)
#pragma unroll
        for (int i = 0; i < 4; i++) o[nt][i] = 0.f;
    float mrun[2] = {-3.0e38f, -3.0e38f};
    float lrun[2] = {0.f, 0.f};

    for (int t = 0; t < NKV; t++) {
        CP_WAIT0();
        __syncthreads();
        if (t + 1 < NKV) {
            load_kv(t + 1);
            CP_COMMIT();
        }
        const uint32_t kb = sKV + (uint32_t)(t & 1) * KV_TILE;

        float s[4][4];
#pragma unroll
        for (int nt = 0; nt < 4; nt++)
#pragma unroll
            for (int i = 0; i < 4; i++) s[nt][i] = 0.f;

#pragma unroll
        for (int kk = 0; kk < 8; kk++) {
            uint32_t qo = (uint32_t)(kk >> 2) * 8192 +
                sw128((w * 16 + (lane & 15)) * 128 +
                      ((kk & 3) * 2 + (lane >> 4)) * 16);
            uint32_t alf[4];
            ldsm4(sQl + qo, alf);
            uint32_t kcol = ((kk & 3) * 2 + ((lane >> 3) & 1)) * 16;
#pragma unroll
            for (int p = 0; p < 2; p++) {
                uint32_t ko = (uint32_t)(kk >> 2) * 4096 +
                    sw128((p * 16 + (lane & 7) + ((lane >> 4) << 3)) * 128 + kcol);
                uint32_t bh[4], bl[4];
                ldsm4(kb + ko, bh);
                ldsm4(kb + 8192 + ko, bl);
#pragma unroll
                for (int q = 0; q < 2; q++) {
                    int nt = p * 2 + q;
                    mma16816(s[nt], ah[kk], &bh[q * 2]);
                    mma16816(s[nt], alf,    &bh[q * 2]);
                    mma16816(s[nt], ah[kk], &bl[q * 2]);
                }
            }
        }

        float tmax[2] = {-3.0e38f, -3.0e38f};
#pragma unroll
        for (int nt = 0; nt < 4; nt++) {
            tmax[0] = fmaxf(tmax[0], fmaxf(s[nt][0], s[nt][1]));
            tmax[1] = fmaxf(tmax[1], fmaxf(s[nt][2], s[nt][3]));
        }
#pragma unroll
        for (int off = 1; off <= 2; off <<= 1) {
            tmax[0] = fmaxf(tmax[0], __shfl_xor_sync(0xffffffffu, tmax[0], off));
            tmax[1] = fmaxf(tmax[1], __shfl_xor_sync(0xffffffffu, tmax[1], off));
        }
        float mnew[2], ci[2];
#pragma unroll
        for (int h = 0; h < 2; h++) {
            mnew[h] = fmaxf(mrun[h], tmax[h]);
            ci[h] = __expf(mrun[h] - mnew[h]);
            mrun[h] = mnew[h];
        }
        uint32_t plo[4], phi[4];
        float rs0 = 0.f, rs1 = 0.f;
#pragma unroll
        for (int nt = 0; nt < 4; nt++) {
            float p0 = __expf(s[nt][0] - mnew[0]);
            float p1 = __expf(s[nt][1] - mnew[0]);
            float p2 = __expf(s[nt][2] - mnew[1]);
            float p3 = __expf(s[nt][3] - mnew[1]);
            rs0 += p0 + p1;
            rs1 += p2 + p3;
            plo[nt] = pack_h2(p0, p1);
            phi[nt] = pack_h2(p2, p3);
        }
        lrun[0] = lrun[0] * ci[0] + rs0;
        lrun[1] = lrun[1] * ci[1] + rs1;
#pragma unroll
        for (int nt = 0; nt < 16; nt++) {
            o[nt][0] *= ci[0];
            o[nt][1] *= ci[0];
            o[nt][2] *= ci[1];
            o[nt][3] *= ci[1];
        }

#pragma unroll
        for (int kk2 = 0; kk2 < 2; kk2++) {
            uint32_t a[4] = {plo[2 * kk2], phi[2 * kk2],
                             plo[2 * kk2 + 1], phi[2 * kk2 + 1]};
            uint32_t kvr = kk2 * 16 + (lane & 7) + (((lane >> 3) & 1) << 3);
#pragma unroll
            for (int dt = 0; dt < 8; dt++) {
                uint32_t dcol = dt * 16 + ((lane >> 4) << 3);
                uint32_t off = (uint32_t)(dcol >> 6) * 4096 +
                               sw128(kvr * 128 + (dcol & 63) * 2);
                uint32_t bv4[4];
                ldsm4t(kb + 16384 + off, bv4);
                mma16816h(o[dt * 2],     a, &bv4[0]);
                mma16816h(o[dt * 2 + 1], a, &bv4[2]);
            }
        }
    }

#pragma unroll
    for (int off = 1; off <= 2; off <<= 1) {
        lrun[0] += __shfl_xor_sync(0xffffffffu, lrun[0], off);
        lrun[1] += __shfl_xor_sync(0xffffffffu, lrun[1], off);
    }
    const float inv0 = 1.0f / lrun[0];
    const float inv1 = 1.0f / lrun[1];
    const int row0 = qt * 64 + w * 16 + (lane >> 2);
    const size_t ob = ((size_t)(b * Nv + n) * Sv) * Dv;
#pragma unroll
    for (int nt = 0; nt < 16; nt++) {
        int d = nt * 8 + (lane & 3) * 2;
        *(float2*)&out[ob + (size_t)row0 * Dv + d] =
            make_float2(o[nt][0] * inv0, o[nt][1] * inv0);
        *(float2*)&out[ob + (size_t)(row0 + 8) * Dv + d] =
            make_float2(o[nt][2] * inv1, o[nt][3] * inv1);
    }
}

// ---------------------------------------------------------------------------
extern "C" void kernel_launch(void* const* d_in, const int* in_sizes, int n_in,
                              void* d_out, int out_size)
{
    const float* hs = (const float*)d_in[0];
    const float* Wq = (const float*)d_in[1];
    const float* bq = (const float*)d_in[2];
    const float* Wk = (const float*)d_in[3];
    const float* bk = (const float*)d_in[4];
    const float* Wv = (const float*)d_in[5];
    const float* bv = (const float*)d_in[6];
    float* out = (float*)d_out;

    conv_kernel<<<CONVA_BLOCKS + CONVB_BLOCKS, 256>>>(hs, Wq, Wk, Wv);

    const int proj_smem = 2 * PSTAGE;   // 64 KB -> 2 CTAs/SM
    cudaFuncSetAttribute(proj_mma_kernel,
                         cudaFuncAttributeMaxDynamicSharedMemorySize, proj_smem);
    proj_mma_kernel<<<dim3(32, 18), 128, proj_smem>>>(bq, bk, bv);

    const int attn_smem = 16384 + 2 * KV_TILE;   // 64 KB -> 3 CTAs/SM
    cudaFuncSetAttribute(attn_mma_kernel,
                         cudaFuncAttributeMaxDynamicSharedMemorySize, attn_smem);
    dim3 ga(Sv / 64, Nv, Bv);
    attn_mma_kernel<<<ga, 128, attn_smem>>>(out);
}

// round 15
// speedup vs baseline: 1.0628x; 1.0197x over previous
#include <cuda_runtime.h>
#include <cuda_bf16.h>
#include <cuda_fp16.h>
#include <cstdint>

#define Bv 4
#define Sv 1024
#define Hv 2048
#define Nv 16
#define Dv 128
#define NCOL 2304          // 18 * 128 fused output columns (16 Q heads, K, V)

// ---------------- device scratch (static: allocation-free) ------------------
__device__ __align__(16) unsigned short g_Ahi[(size_t)Bv * Sv * Hv];
__device__ __align__(16) unsigned short g_Alo[(size_t)Bv * Sv * Hv];
__device__ __align__(16) unsigned short g_Bhi[(size_t)NCOL * Hv];
__device__ __align__(16) unsigned short g_Blo[(size_t)NCOL * Hv];
__device__ __align__(16) unsigned short g_Qh[(size_t)Bv * Nv * Sv * Dv];
__device__ __align__(16) unsigned short g_Ql[(size_t)Bv * Nv * Sv * Dv];
__device__ __align__(16) unsigned short g_Kh[(size_t)Bv * Sv * Dv];
__device__ __align__(16) unsigned short g_Kl[(size_t)Bv * Sv * Dv];
__device__ __align__(16) __half         g_Vf[(size_t)Bv * Sv * Dv];

// ---------------- helpers ----------------------------------------------------
__device__ __forceinline__ uint32_t smem_u32(const void* p) {
    uint32_t a;
    asm("{ .reg .u64 t; cvta.to.shared.u64 t, %1; cvt.u32.u64 %0, t; }"
        : "=r"(a) : "l"(p));
    return a;
}
__device__ __forceinline__ uint32_t sw128(uint32_t b) {
    return b ^ ((b >> 3) & 0x70);
}
__device__ __forceinline__ uint32_t sw64(uint32_t b) {
    return b ^ (((b >> 7) & 3u) << 4);
}
#define CP16(dst, src) asm volatile( \
    "cp.async.cg.shared.global [%0], [%1], 16;" :: "r"(dst), "l"(src))
#define CP_COMMIT() asm volatile("cp.async.commit_group;" ::: "memory")
#define CP_WAIT0() asm volatile("cp.async.wait_group 0;" ::: "memory")

__device__ __forceinline__ void ldsm4(uint32_t addr, uint32_t* r) {
    asm volatile("ldmatrix.sync.aligned.m8n8.x4.shared.b16 {%0,%1,%2,%3}, [%4];"
                 : "=r"(r[0]), "=r"(r[1]), "=r"(r[2]), "=r"(r[3]) : "r"(addr));
}
__device__ __forceinline__ void ldsm4t(uint32_t addr, uint32_t* r) {
    asm volatile("ldmatrix.sync.aligned.m8n8.x4.trans.shared.b16 {%0,%1,%2,%3}, [%4];"
                 : "=r"(r[0]), "=r"(r[1]), "=r"(r[2]), "=r"(r[3]) : "r"(addr));
}
__device__ __forceinline__ void mma16816(float* d, const uint32_t* a,
                                         const uint32_t* b) {
    asm volatile(
        "mma.sync.aligned.m16n8k16.row.col.f32.bf16.bf16.f32 "
        "{%0,%1,%2,%3}, {%4,%5,%6,%7}, {%8,%9}, {%0,%1,%2,%3};"
        : "+f"(d[0]), "+f"(d[1]), "+f"(d[2]), "+f"(d[3])
        : "r"(a[0]), "r"(a[1]), "r"(a[2]), "r"(a[3]), "r"(b[0]), "r"(b[1]));
}
__device__ __forceinline__ void mma16816h(float* d, const uint32_t* a,
                                          const uint32_t* b) {
    asm volatile(
        "mma.sync.aligned.m16n8k16.row.col.f32.f16.f16.f32 "
        "{%0,%1,%2,%3}, {%4,%5,%6,%7}, {%8,%9}, {%0,%1,%2,%3};"
        : "+f"(d[0]), "+f"(d[1]), "+f"(d[2]), "+f"(d[3])
        : "r"(a[0]), "r"(a[1]), "r"(a[2]), "r"(a[3]), "r"(b[0]), "r"(b[1]));
}

__device__ __forceinline__ void split_bf16(float x, unsigned short& h,
                                           unsigned short& l) {
    __nv_bfloat16 hb = __float2bfloat16_rn(x);
    __nv_bfloat16 lb = __float2bfloat16_rn(x - __bfloat162float(hb));
    h = *(unsigned short*)&hb;
    l = *(unsigned short*)&lb;
}
__device__ __forceinline__ uint32_t pack_h2(float a, float b) {
    __half2 h = __floats2half2_rn(a, b);
    return *(uint32_t*)&h;
}

// ---------------------------------------------------------------------------
// Merged convert kernel (R14 form — measured 17.7us).
// Blocks [0, CONVA_BLOCKS): hidden_states -> Ahi/Alo.
// Blocks [CONVA_BLOCKS, ...): W transpose -> Bhi/Blo (32x32 smem tiles).
// ---------------------------------------------------------------------------
#define CONVA_BLOCKS ((Bv * Sv * Hv / 4) / 256)          // 8192
#define CONVB_BLOCKS ((NCOL / 32) * (Hv / 32))           // 4608

__global__ void conv_kernel(const float* __restrict__ hs,
                            const float* __restrict__ Wq,
                            const float* __restrict__ Wk,
                            const float* __restrict__ Wv) {
    __shared__ float t[32][33];
    const int bid = blockIdx.x;
    const int tid = threadIdx.x;

    if (bid < CONVA_BLOCKS) {
        size_t i4 = (size_t)bid * 256 + tid;
        float4 x = *(const float4*)&hs[i4 * 4];
        unsigned short h[4], l[4];
        split_bf16(x.x, h[0], l[0]);
        split_bf16(x.y, h[1], l[1]);
        split_bf16(x.z, h[2], l[2]);
        split_bf16(x.w, h[3], l[3]);
        *(uint2*)&g_Ahi[i4 * 4] = *(uint2*)h;
        *(uint2*)&g_Alo[i4 * 4] = *(uint2*)l;
        return;
    }

    const int bid2 = bid - CONVA_BLOCKS;
    const int n0 = (bid2 % (NCOL / 32)) * 32;
    const int k0 = (bid2 / (NCOL / 32)) * 32;
    const int tx = tid & 31;
    const int ty = tid >> 5;
    const int u = n0 >> 7;
    const int d0 = n0 & 127;
    const float* W = (u < Nv) ? (Wq + (size_t)u * Hv * Dv)
                              : ((u == Nv) ? Wk : Wv);
#pragma unroll
    for (int i = 0; i < 4; i++) {
        int k = k0 + ty + i * 8;
        t[ty + i * 8][tx] = W[(size_t)k * Dv + d0 + tx];
    }
    __syncthreads();
#pragma unroll
    for (int i = 0; i < 4; i++) {
        int r = ty + i * 8;
        float v = t[tx][r];
        unsigned short h, l;
        split_bf16(v, h, l);
        size_t o = (size_t)(n0 + r) * Hv + k0 + tx;
        g_Bhi[o] = h;
        g_Blo[o] = l;
    }
}

// ---------------------------------------------------------------------------
// bf16x3 projection GEMM (HMMA), 2 CTAs/SM, 2-stage pipeline (R11 form).
// CTA tile 128x128 (grid 32 x 18), 128 threads, warp tile 64x64, k32 (SW64).
// ---------------------------------------------------------------------------
#define PSTAGE 32768
#define NCHUNK 64

__global__ __launch_bounds__(128, 2) void proj_mma_kernel(
    const float* __restrict__ bq, const float* __restrict__ bk,
    const float* __restrict__ bv)
{
    extern __shared__ __align__(1024) char smem[];
    const int tid = threadIdx.x;
    const int lane = tid & 31;
    const int w = tid >> 5;
    const int wm = w & 1;
    const int wn = w >> 1;
    const int m0 = blockIdx.x * 128;
    const int by = blockIdx.y;
    const int n0 = by * 128;
    const uint32_t sbase = smem_u32(smem);

    float acc[4][8][4];
#pragma unroll
    for (int mt = 0; mt < 4; mt++)
#pragma unroll
        for (int nt = 0; nt < 8; nt++)
#pragma unroll
            for (int i = 0; i < 4; i++) acc[mt][nt][i] = 0.f;

    auto load_chunk = [&](uint32_t sb, int c) {
        const int k0 = c * 32;
#pragma unroll
        for (int i = 0; i < 4; i++) {
            int idx = tid + 128 * i;
            int r = idx >> 2, col = idx & 3;
            uint32_t off = sw64(r * 64 + col * 16);
            CP16(sb + off,         &g_Ahi[(size_t)(m0 + r) * Hv + k0 + col * 8]);
            CP16(sb + 8192 + off,  &g_Alo[(size_t)(m0 + r) * Hv + k0 + col * 8]);
            CP16(sb + 16384 + off, &g_Bhi[(size_t)(n0 + r) * Hv + k0 + col * 8]);
            CP16(sb + 24576 + off, &g_Blo[(size_t)(n0 + r) * Hv + k0 + col * 8]);
        }
    };

    const int a_row = wm * 64 + (lane & 15);
    const int a_k16 = lane >> 4;
    const int b_row0 = wn * 64 + (lane & 7) + ((lane >> 4) << 3);
    const int b_k16 = (lane >> 3) & 1;

    load_chunk(sbase, 0);
    CP_COMMIT();

    for (int c = 0; c < NCHUNK; c++) {
        const uint32_t sb = sbase + (uint32_t)(c & 1) * PSTAGE;
        CP_WAIT0();
        __syncthreads();
        if (c + 1 < NCHUNK) {
            load_chunk(sbase + (uint32_t)((c + 1) & 1) * PSTAGE, c + 1);
            CP_COMMIT();
        }

#pragma unroll
        for (int ks = 0; ks < 2; ks++) {
            uint32_t ah[4][4], al[4][4], bh[4][4], bl[4][4];
#pragma unroll
            for (int mt = 0; mt < 4; mt++) {
                uint32_t off = sw64((a_row + mt * 16) * 64 +
                                    (ks * 2 + a_k16) * 16);
                ldsm4(sb + off, ah[mt]);
                ldsm4(sb + 8192 + off, al[mt]);
            }
#pragma unroll
            for (int p = 0; p < 4; p++) {
                uint32_t off = sw64((b_row0 + p * 16) * 64 +
                                    (ks * 2 + b_k16) * 16);
                ldsm4(sb + 16384 + off, bh[p]);
                ldsm4(sb + 24576 + off, bl[p]);
            }
#pragma unroll
            for (int mt = 0; mt < 4; mt++)
#pragma unroll
                for (int nt = 0; nt < 8; nt++) {
                    const uint32_t* bhp = &bh[nt >> 1][(nt & 1) * 2];
                    const uint32_t* blp = &bl[nt >> 1][(nt & 1) * 2];
                    mma16816(acc[mt][nt], ah[mt], bhp);
                    mma16816(acc[mt][nt], al[mt], bhp);
                    mma16816(acc[mt][nt], ah[mt], blp);
                }
        }
    }

    const int u = by;
    const float* bias = (u < Nv) ? (bq + u * Dv) : ((u == Nv) ? bk : bv);
    const int qrow = lane >> 2;
    const int qcol = (lane & 3) * 2;

#pragma unroll
    for (int mt = 0; mt < 4; mt++) {
#pragma unroll
        for (int half = 0; half < 2; half++) {
            int mrow = m0 + wm * 64 + mt * 16 + qrow + half * 8;
            size_t base;
            if (u < Nv) {
                int b = mrow >> 10, s = mrow & 1023;
                base = ((size_t)(b * Nv + u) * Sv + s) * Dv;
            } else {
                base = (size_t)mrow * Dv;
            }
#pragma unroll
            for (int nt = 0; nt < 8; nt++) {
                int d = wn * 64 + nt * 8 + qcol;
                float x = acc[mt][nt][half * 2 + 0] + bias[d];
                float y = acc[mt][nt][half * 2 + 1] + bias[d + 1];
                if (u < Nv) {
                    unsigned short hx, lx, hy, ly;
                    split_bf16(x, hx, lx);
                    split_bf16(y, hy, ly);
                    *(ushort2*)&g_Qh[base + d] = make_ushort2(hx, hy);
                    *(ushort2*)&g_Ql[base + d] = make_ushort2(lx, ly);
                } else if (u == Nv) {
                    unsigned short hx, lx, hy, ly;
                    split_bf16(x, hx, lx);
                    split_bf16(y, hy, ly);
                    *(ushort2*)&g_Kh[base + d] = make_ushort2(hx, hy);
                    *(ushort2*)&g_Kl[base + d] = make_ushort2(lx, ly);
                } else {
                    __half2 v2 = __floats2half2_rn(x, y);
                    *(__half2*)&g_Vf[base + d] = v2;
                }
            }
        }
    }
}

// ---------------------------------------------------------------------------
// Tensor-core flash attention (R10/R11 form — best total-time measured).
// 128 threads (4 warps x 16 q-rows = 64-row q tiles), 64-key KV tiles,
// 112KB smem/CTA -> 2 CTAs/SM. grid (S/64, N, B) = 1024 CTAs.
// ---------------------------------------------------------------------------
#define KV_TILE 49152
#define NKV (Sv / 64)

__global__ __launch_bounds__(128, 2) void attn_mma_kernel(float* __restrict__ out)
{
    extern __shared__ __align__(1024) char smem[];
    const int tid = threadIdx.x;
    const int lane = tid & 31;
    const int w = tid >> 5;
    const int qt = blockIdx.x;
    const int n = blockIdx.y;
    const int b = blockIdx.z;

    const uint32_t sQl = smem_u32(smem);
    const uint32_t sKV = sQl + 16384;

    const size_t qoff = ((size_t)(b * Nv + n) * Sv + qt * 64) * Dv;
    const unsigned short* Qhp = g_Qh + qoff;
    const unsigned short* Qlp = g_Ql + qoff;
#pragma unroll
    for (int i = 0; i < 8; i++) {
        int idx = tid + 128 * i;
        int r = idx >> 4, c16 = idx & 15;
        uint32_t off = (uint32_t)(c16 >> 3) * 8192 +
                       sw128(r * 128 + (c16 & 7) * 16);
        CP16(sKV + off, Qhp + (size_t)r * Dv + c16 * 8);
        CP16(sQl + off, Qlp + (size_t)r * Dv + c16 * 8);
    }
    CP_COMMIT();
    CP_WAIT0();
    __syncthreads();

    uint32_t ah[8][4];
#pragma unroll
    for (int kk = 0; kk < 8; kk++) {
        uint32_t qo = (uint32_t)(kk >> 2) * 8192 +
            sw128((w * 16 + (lane & 15)) * 128 +
                  ((kk & 3) * 2 + (lane >> 4)) * 16);
        ldsm4(sKV + qo, ah[kk]);
    }
    __syncthreads();

    const unsigned short* Kh = g_Kh + (size_t)b * Sv * Dv;
    const unsigned short* Kl = g_Kl + (size_t)b * Sv * Dv;
    const __half* Vf = g_Vf + (size_t)b * Sv * Dv;

    auto load_kv = [&](int t) {
        uint32_t dst = sKV + (uint32_t)(t & 1) * KV_TILE;
        int r0 = t * 64;
#pragma unroll
        for (int i = 0; i < 8; i++) {
            int idx = tid + 128 * i;
            int r = idx >> 4, c16 = idx & 15;
            uint32_t off = (uint32_t)(c16 >> 3) * 8192 +
                           sw128(r * 128 + (c16 & 7) * 16);
            CP16(dst + off,         Kh + (size_t)(r0 + r) * Dv + c16 * 8);
            CP16(dst + 16384 + off, Kl + (size_t)(r0 + r) * Dv + c16 * 8);
            CP16(dst + 32768 + off, Vf + (size_t)(r0 + r) * Dv + c16 * 8);
        }
    };

    load_kv(0);
    CP_COMMIT();

    float o[16][4];
#pragma unroll
    for (int nt = 0; nt < 16; nt++)
#pragma unroll
        for (int i = 0; i < 4; i++) o[nt][i] = 0.f;
    float mrun[2] = {-3.0e38f, -3.0e38f};
    float lrun[2] = {0.f, 0.f};

    for (int t = 0; t < NKV; t++) {
        CP_WAIT0();
        __syncthreads();
        if (t + 1 < NKV) {
            load_kv(t + 1);
            CP_COMMIT();
        }
        const uint32_t kb = sKV + (uint32_t)(t & 1) * KV_TILE;

        float s[8][4];
#pragma unroll
        for (int nt = 0; nt < 8; nt++)
#pragma unroll
            for (int i = 0; i < 4; i++) s[nt][i] = 0.f;

#pragma unroll
        for (int kk = 0; kk < 8; kk++) {
            uint32_t qo = (uint32_t)(kk >> 2) * 8192 +
                sw128((w * 16 + (lane & 15)) * 128 +
                      ((kk & 3) * 2 + (lane >> 4)) * 16);
            uint32_t alf[4];
            ldsm4(sQl + qo, alf);
            uint32_t kcol = ((kk & 3) * 2 + ((lane >> 3) & 1)) * 16;
#pragma unroll
            for (int p = 0; p < 4; p++) {
                uint32_t ko = (uint32_t)(kk >> 2) * 8192 +
                    sw128((p * 16 + (lane & 7) + ((lane >> 4) << 3)) * 128 + kcol);
                uint32_t bh[4], bl[4];
                ldsm4(kb + ko, bh);
                ldsm4(kb + 16384 + ko, bl);
#pragma unroll
                for (int q = 0; q < 2; q++) {
                    int nt = p * 2 + q;
                    mma16816(s[nt], ah[kk], &bh[q * 2]);
                    mma16816(s[nt], alf,    &bh[q * 2]);
                    mma16816(s[nt], ah[kk], &bl[q * 2]);
                }
            }
        }

        float tmax[2] = {-3.0e38f, -3.0e38f};
#pragma unroll
        for (int nt = 0; nt < 8; nt++) {
            tmax[0] = fmaxf(tmax[0], fmaxf(s[nt][0], s[nt][1]));
            tmax[1] = fmaxf(tmax[1], fmaxf(s[nt][2], s[nt][3]));
        }
#pragma unroll
        for (int off = 1; off <= 2; off <<= 1) {
            tmax[0] = fmaxf(tmax[0], __shfl_xor_sync(0xffffffffu, tmax[0], off));
            tmax[1] = fmaxf(tmax[1], __shfl_xor_sync(0xffffffffu, tmax[1], off));
        }
        float mnew[2], ci[2];
#pragma unroll
        for (int h = 0; h < 2; h++) {
            mnew[h] = fmaxf(mrun[h], tmax[h]);
            ci[h] = __expf(mrun[h] - mnew[h]);
            mrun[h] = mnew[h];
        }
        uint32_t plo[8], phi[8];
        float rs0 = 0.f, rs1 = 0.f;
#pragma unroll
        for (int nt = 0; nt < 8; nt++) {
            float p0 = __expf(s[nt][0] - mnew[0]);
            float p1 = __expf(s[nt][1] - mnew[0]);
            float p2 = __expf(s[nt][2] - mnew[1]);
            float p3 = __expf(s[nt][3] - mnew[1]);
            rs0 += p0 + p1;
            rs1 += p2 + p3;
            plo[nt] = pack_h2(p0, p1);
            phi[nt] = pack_h2(p2, p3);
        }
        lrun[0] = lrun[0] * ci[0] + rs0;
        lrun[1] = lrun[1] * ci[1] + rs1;
#pragma unroll
        for (int nt = 0; nt < 16; nt++) {
            o[nt][0] *= ci[0];
            o[nt][1] *= ci[0];
            o[nt][2] *= ci[1];
            o[nt][3] *= ci[1];
        }

#pragma unroll
        for (int kk2 = 0; kk2 < 4; kk2++) {
            uint32_t a[4] = {plo[2 * kk2], phi[2 * kk2],
                             plo[2 * kk2 + 1], phi[2 * kk2 + 1]};
            uint32_t kvr = kk2 * 16 + (lane & 7) + (((lane >> 3) & 1) << 3);
#pragma unroll
            for (int dt = 0; dt < 8; dt++) {
                uint32_t dcol = dt * 16 + ((lane >> 4) << 3);
                uint32_t off = (uint32_t)(dcol >> 6) * 8192 +
                               sw128(kvr * 128 + (dcol & 63) * 2);
                uint32_t bv4[4];
                ldsm4t(kb + 32768 + off, bv4);
                mma16816h(o[dt * 2],     a, &bv4[0]);
                mma16816h(o[dt * 2 + 1], a, &bv4[2]);
            }
        }
    }

#pragma unroll
    for (int off = 1; off <= 2; off <<= 1) {
        lrun[0] += __shfl_xor_sync(0xffffffffu, lrun[0], off);
        lrun[1] += __shfl_xor_sync(0xffffffffu, lrun[1], off);
    }
    const float inv0 = 1.0f / lrun[0];
    const float inv1 = 1.0f / lrun[1];
    const int row0 = qt * 64 + w * 16 + (lane >> 2);
    const size_t ob = ((size_t)(b * Nv + n) * Sv) * Dv;
#pragma unroll
    for (int nt = 0; nt < 16; nt++) {
        int d = nt * 8 + (lane & 3) * 2;
        *(float2*)&out[ob + (size_t)row0 * Dv + d] =
            make_float2(o[nt][0] * inv0, o[nt][1] * inv0);
        *(float2*)&out[ob + (size_t)(row0 + 8) * Dv + d] =
            make_float2(o[nt][2] * inv1, o[nt][3] * inv1);
    }
}

// ---------------------------------------------------------------------------
extern "C" void kernel_launch(void* const* d_in, const int* in_sizes, int n_in,
                              void* d_out, int out_size)
{
    const float* hs = (const float*)d_in[0];
    const float* Wq = (const float*)d_in[1];
    const float* bq = (const float*)d_in[2];
    const float* Wk = (const float*)d_in[3];
    const float* bk = (const float*)d_in[4];
    const float* Wv = (const float*)d_in[5];
    const float* bv = (const float*)d_in[6];
    float* out = (float*)d_out;

    conv_kernel<<<CONVA_BLOCKS + CONVB_BLOCKS, 256>>>(hs, Wq, Wk, Wv);

    const int proj_smem = 2 * PSTAGE;   // 64 KB -> 2 CTAs/SM
    cudaFuncSetAttribute(proj_mma_kernel,
                         cudaFuncAttributeMaxDynamicSharedMemorySize, proj_smem);
    proj_mma_kernel<<<dim3(32, 18), 128, proj_smem>>>(bq, bk, bv);

    const int attn_smem = 16384 + 2 * KV_TILE;   // 112 KB -> 2 CTAs/SM
    cudaFuncSetAttribute(attn_mma_kernel,
                         cudaFuncAttributeMaxDynamicSharedMemorySize, attn_smem);
    dim3 ga(Sv / 64, Nv, Bv);
    attn_mma_kernel<<<ga, 128, attn_smem>>>(out);
}